// round 2
// baseline (speedup 1.0000x reference)
#include <cuda_runtime.h>

#define N_NODES 100000
#define E_MAX   3400000

// ---------------- scratch (device globals; no allocation allowed) ------------
__device__ int   g_cnt[N_NODES];
__device__ int   g_cursor[N_NODES];
__device__ float g_dinv[N_NODES];
__device__ int   g_rowptr[N_NODES + 1];
__device__ int   g_csr[E_MAX];                       // src indices grouped by dst
__device__ __align__(16) float g_h1[(size_t)N_NODES * 128];
__device__ __align__(16) float g_a1[(size_t)N_NODES * 128];
__device__ __align__(16) float g_h2[(size_t)N_NODES * 64];
__device__ int   g_is64;

// ---------------- init + edge dtype detection --------------------------------
// Zeros counters; block 0 additionally samples the edge buffer interpreted as
// int64 — any value outside [0, N) means the data is actually int32.
__global__ void prep_init_kernel(const long long* __restrict__ edges) {
    int i = blockIdx.x * blockDim.x + threadIdx.x;
    if (i < N_NODES) { g_cnt[i] = 0; g_cursor[i] = 0; }
    if (blockIdx.x == 0) {
        __shared__ int bad;
        if (threadIdx.x == 0) bad = 0;
        __syncthreads();
        for (int k = threadIdx.x; k < 1024; k += blockDim.x) {
            long long v = edges[k];
            if (v < 0 || v >= N_NODES) bad = 1;   // benign race: all writers store 1
        }
        __syncthreads();
        if (threadIdx.x == 0) g_is64 = bad ? 0 : 1;
    }
}

// count in-degree, reading dst directly from the raw edge buffer
__global__ void count_kernel(const void* __restrict__ edges, int E) {
    int e = blockIdx.x * blockDim.x + threadIdx.x;
    if (e >= E) return;
    int d;
    if (g_is64) d = (int)((const long long*)edges)[(size_t)E + e];
    else        d = ((const int*)edges)[E + e];
    atomicAdd(&g_cnt[d], 1);
}

__global__ void dinv_kernel() {
    int i = blockIdx.x * blockDim.x + threadIdx.x;
    if (i < N_NODES) g_dinv[i] = rsqrtf((float)(g_cnt[i] + 1));  // +1 = self loop
}

// single-block exclusive scan of g_cnt -> g_rowptr
__global__ void scan_kernel() {
    __shared__ int ssum[1024];
    const int n = N_NODES;
    int tid = threadIdx.x;
    const int per = (n + 1023) / 1024;
    int start = tid * per;
    int end = start + per; if (end > n) end = n;
    int s = 0;
    for (int i = start; i < end; i++) s += g_cnt[i];
    ssum[tid] = s;
    __syncthreads();
    for (int off = 1; off < 1024; off <<= 1) {
        int v = (tid >= off) ? ssum[tid - off] : 0;
        __syncthreads();
        ssum[tid] += v;
        __syncthreads();
    }
    int run = ssum[tid] - s;  // exclusive prefix of this chunk
    for (int i = start; i < end; i++) { g_rowptr[i] = run; run += g_cnt[i]; }
    if (tid == 1023) g_rowptr[n] = ssum[1023];
}

__global__ void fill_kernel(const void* __restrict__ edges, int E) {
    int e = blockIdx.x * blockDim.x + threadIdx.x;
    if (e >= E) return;
    int s, d;
    if (g_is64) {
        const long long* p = (const long long*)edges;
        s = (int)p[e];
        d = (int)p[(size_t)E + e];
    } else {
        const int* p = (const int*)edges;
        s = p[e];
        d = p[E + e];
    }
    int pos = g_rowptr[d] + atomicAdd(&g_cursor[d], 1);
    g_csr[pos] = s;
}

// ---------------- GEMM: Y[N, DOUT] = X[N,128] @ W[128, DOUT] ----------------
// W fully staged in SMEM; 32 rows/block, 8 warps, 4 rows/warp, DOUT/32 cols/lane.
template <int DOUT>
__global__ void gemm_kernel(const float* __restrict__ X, const float* __restrict__ W,
                            float* __restrict__ Y) {
    extern __shared__ float smem[];
    float* sW = smem;                // 128 * DOUT
    float* sX = smem + 128 * DOUT;   // 32 * 128
    int tid = threadIdx.x, wid = tid >> 5, lane = tid & 31;

    for (int i = tid * 4; i < 128 * DOUT; i += 1024)
        *(float4*)&sW[i] = *(const float4*)&W[i];
    int row0 = blockIdx.x * 32;
    for (int i = tid * 4; i < 32 * 128; i += 1024)
        *(float4*)&sX[i] = *(const float4*)&X[(size_t)row0 * 128 + i];
    __syncthreads();

    constexpr int V = DOUT / 32;     // 4 (DOUT=128) or 2 (DOUT=64)
    float acc[4][V];
#pragma unroll
    for (int r = 0; r < 4; r++)
#pragma unroll
        for (int c = 0; c < V; c++) acc[r][c] = 0.0f;

    int r0 = wid * 4;
#pragma unroll 4
    for (int k = 0; k < 128; k++) {
        float wv[V];
        if constexpr (V == 4) {
            float4 t = *(float4*)&sW[k * DOUT + lane * 4];
            wv[0] = t.x; wv[1] = t.y; wv[2] = t.z; wv[3] = t.w;
        } else {
            float2 t = *(float2*)&sW[k * DOUT + lane * 2];
            wv[0] = t.x; wv[1] = t.y;
        }
        float xv[4];
#pragma unroll
        for (int r = 0; r < 4; r++) xv[r] = sX[(r0 + r) * 128 + k];
#pragma unroll
        for (int r = 0; r < 4; r++)
#pragma unroll
            for (int c = 0; c < V; c++) acc[r][c] += xv[r] * wv[c];
    }

#pragma unroll
    for (int r = 0; r < 4; r++) {
        float* yp = &Y[(size_t)(row0 + r0 + r) * DOUT + lane * V];
        if constexpr (V == 4) *(float4*)yp = make_float4(acc[r][0], acc[r][1], acc[r][2], acc[r][3]);
        else                  *(float2*)yp = make_float2(acc[r][0], acc[r][1]);
    }
}

// ---------------- aggregation: one warp per destination node ----------------
// out[n] = dinv[n]*sum_{s in N(n)} dinv[s]*H[s] + dinv[n]^2*H[n] + bias  (opt relu)
// 2-edge unroll: both gather rows issued before the FMAs -> 2x MLP per warp.
template <int D, bool RELU>
__global__ void agg_kernel(const float* __restrict__ H, const float* __restrict__ bias,
                           float* __restrict__ OUT) {
    int gw = (blockIdx.x * blockDim.x + threadIdx.x) >> 5;
    if (gw >= N_NODES) return;
    int lane = threadIdx.x & 31;
    constexpr int V = D / 32;

    float acc[V];
#pragma unroll
    for (int c = 0; c < V; c++) acc[c] = 0.0f;

    int e = g_rowptr[gw];
    const int e1 = g_rowptr[gw + 1];

    for (; e + 1 < e1; e += 2) {
        int s0 = __ldg(&g_csr[e]);
        int s1 = __ldg(&g_csr[e + 1]);
        float w0 = __ldg(&g_dinv[s0]);
        float w1 = __ldg(&g_dinv[s1]);
        if constexpr (V == 4) {
            float4 a = *(const float4*)&H[(size_t)s0 * D + lane * 4];
            float4 b = *(const float4*)&H[(size_t)s1 * D + lane * 4];
            acc[0] += w0 * a.x + w1 * b.x;
            acc[1] += w0 * a.y + w1 * b.y;
            acc[2] += w0 * a.z + w1 * b.z;
            acc[3] += w0 * a.w + w1 * b.w;
        } else {
            float2 a = *(const float2*)&H[(size_t)s0 * D + lane * 2];
            float2 b = *(const float2*)&H[(size_t)s1 * D + lane * 2];
            acc[0] += w0 * a.x + w1 * b.x;
            acc[1] += w0 * a.y + w1 * b.y;
        }
    }
    if (e < e1) {
        int s = __ldg(&g_csr[e]);
        float w = __ldg(&g_dinv[s]);
        if constexpr (V == 4) {
            float4 a = *(const float4*)&H[(size_t)s * D + lane * 4];
            acc[0] += w * a.x; acc[1] += w * a.y; acc[2] += w * a.z; acc[3] += w * a.w;
        } else {
            float2 a = *(const float2*)&H[(size_t)s * D + lane * 2];
            acc[0] += w * a.x; acc[1] += w * a.y;
        }
    }

    float dd = g_dinv[gw];
    float dd2 = dd * dd;
    if constexpr (V == 4) {
        float4 hs = *(const float4*)&H[(size_t)gw * D + lane * 4];
        float4 bv = *(const float4*)&bias[lane * 4];
        float o0 = dd * acc[0] + dd2 * hs.x + bv.x;
        float o1 = dd * acc[1] + dd2 * hs.y + bv.y;
        float o2 = dd * acc[2] + dd2 * hs.z + bv.z;
        float o3 = dd * acc[3] + dd2 * hs.w + bv.w;
        if constexpr (RELU) {
            o0 = fmaxf(o0, 0.0f); o1 = fmaxf(o1, 0.0f);
            o2 = fmaxf(o2, 0.0f); o3 = fmaxf(o3, 0.0f);
        }
        *(float4*)&OUT[(size_t)gw * D + lane * 4] = make_float4(o0, o1, o2, o3);
    } else {
        float2 hs = *(const float2*)&H[(size_t)gw * D + lane * 2];
        float2 bv = *(const float2*)&bias[lane * 2];
        float o0 = dd * acc[0] + dd2 * hs.x + bv.x;
        float o1 = dd * acc[1] + dd2 * hs.y + bv.y;
        if constexpr (RELU) { o0 = fmaxf(o0, 0.0f); o1 = fmaxf(o1, 0.0f); }
        *(float2*)&OUT[(size_t)gw * D + lane * 2] = make_float2(o0, o1);
    }
}

// ---------------- launch -----------------------------------------------------
extern "C" void kernel_launch(void* const* d_in, const int* in_sizes, int n_in,
                              void* d_out, int out_size) {
    const float* x  = (const float*)d_in[0];
    const void*  ei = d_in[1];
    const float* W1 = (const float*)d_in[2];
    const float* b1 = (const float*)d_in[3];
    const float* W2 = (const float*)d_in[4];
    const float* b2 = (const float*)d_in[5];
    float* out = (float*)d_out;
    int E = in_sizes[1] / 2;   // element count of (2, E) regardless of int32/int64

    const int SMEM1 = (128 * 128 + 32 * 128) * 4;   // 80 KB
    const int SMEM2 = (128 * 64 + 32 * 128) * 4;    // 48 KB
    cudaFuncSetAttribute(gemm_kernel<128>, cudaFuncAttributeMaxDynamicSharedMemorySize, SMEM1);
    cudaFuncSetAttribute(gemm_kernel<64>,  cudaFuncAttributeMaxDynamicSharedMemorySize, SMEM2);

    float *h1, *a1, *h2;
    cudaGetSymbolAddress((void**)&h1, g_h1);
    cudaGetSymbolAddress((void**)&a1, g_a1);
    cudaGetSymbolAddress((void**)&h2, g_h2);

    const int TB = 256;
    int gE = (E + TB - 1) / TB;
    int gN = (N_NODES + TB - 1) / TB;

    // Fork a non-blocking side stream: gemm1 (x@W1, independent of the graph
    // structure) runs concurrently with the CSR build; joined via event before
    // agg1. Handles are intentionally not destroyed mid-capture.
    cudaStream_t s2;
    cudaStreamCreateWithFlags(&s2, cudaStreamNonBlocking);
    cudaEvent_t ev0, ev1;
    cudaEventCreateWithFlags(&ev0, cudaEventDisableTiming);
    cudaEventCreateWithFlags(&ev1, cudaEventDisableTiming);

    cudaEventRecord(ev0, 0);
    cudaStreamWaitEvent(s2, ev0, 0);
    gemm_kernel<128><<<N_NODES / 32, 256, SMEM1, s2>>>(x, W1, h1);
    cudaEventRecord(ev1, s2);

    // CSR-build branch on the main stream
    prep_init_kernel<<<gN, TB>>>((const long long*)ei);
    count_kernel<<<gE, TB>>>(ei, E);
    dinv_kernel<<<gN, TB>>>();
    scan_kernel<<<1, 1024>>>();
    fill_kernel<<<gE, TB>>>(ei, E);

    cudaStreamWaitEvent(0, ev1, 0);   // join: agg1 needs both CSR and h1

    agg_kernel<128, true><<<(N_NODES + 7) / 8, 256>>>(h1, b1, a1);
    gemm_kernel<64><<<N_NODES / 32, 256, SMEM2>>>(a1, W2, h2);
    agg_kernel<64, false><<<(N_NODES + 7) / 8, 256>>>(h2, b2, out);
}

// round 5
// speedup vs baseline: 1.5798x; 1.5798x over previous
#include <cuda_runtime.h>
#include <cuda_fp16.h>

#define N_NODES 100000
#define E_MAX   3400000

// ---------------- scratch (device globals; no allocation allowed) ------------
__device__ int   g_cnt[N_NODES];
__device__ int   g_cursor[N_NODES];
__device__ float g_dinv[N_NODES];
__device__ int   g_rowptr[N_NODES + 1];
__device__ int   g_csr[E_MAX];                       // src indices grouped by dst
__device__ __align__(16) __half g_h1[(size_t)N_NODES * 128];  // fp16 features for gather
__device__ __align__(16) float  g_a1[(size_t)N_NODES * 128];  // fp32 layer-1 output
__device__ __align__(16) __half g_h2[(size_t)N_NODES * 64];
__device__ int   g_is64;

// ---------------- init + edge dtype detection --------------------------------
__global__ void prep_init_kernel(const long long* __restrict__ edges) {
    int i = blockIdx.x * blockDim.x + threadIdx.x;
    if (i < N_NODES) { g_cnt[i] = 0; g_cursor[i] = 0; }
    if (blockIdx.x == 0) {
        __shared__ int bad;
        if (threadIdx.x == 0) bad = 0;
        __syncthreads();
        for (int k = threadIdx.x; k < 1024; k += blockDim.x) {
            long long v = edges[k];
            if (v < 0 || v >= N_NODES) bad = 1;   // benign race: all writers store 1
        }
        __syncthreads();
        if (threadIdx.x == 0) g_is64 = bad ? 0 : 1;
    }
}

__global__ void count_kernel(const void* __restrict__ edges, int E) {
    int e = blockIdx.x * blockDim.x + threadIdx.x;
    if (e >= E) return;
    int d;
    if (g_is64) d = (int)((const long long*)edges)[(size_t)E + e];
    else        d = ((const int*)edges)[E + e];
    atomicAdd(&g_cnt[d], 1);
}

__global__ void dinv_kernel() {
    int i = blockIdx.x * blockDim.x + threadIdx.x;
    if (i < N_NODES) g_dinv[i] = rsqrtf((float)(g_cnt[i] + 1));  // +1 = self loop
}

// single-block exclusive scan of g_cnt -> g_rowptr
__global__ void scan_kernel() {
    __shared__ int ssum[1024];
    const int n = N_NODES;
    int tid = threadIdx.x;
    const int per = (n + 1023) / 1024;
    int start = tid * per;
    int end = start + per; if (end > n) end = n;
    int s = 0;
    for (int i = start; i < end; i++) s += g_cnt[i];
    ssum[tid] = s;
    __syncthreads();
    for (int off = 1; off < 1024; off <<= 1) {
        int v = (tid >= off) ? ssum[tid - off] : 0;
        __syncthreads();
        ssum[tid] += v;
        __syncthreads();
    }
    int run = ssum[tid] - s;
    for (int i = start; i < end; i++) { g_rowptr[i] = run; run += g_cnt[i]; }
    if (tid == 1023) g_rowptr[n] = ssum[1023];
}

__global__ void fill_kernel(const void* __restrict__ edges, int E) {
    int e = blockIdx.x * blockDim.x + threadIdx.x;
    if (e >= E) return;
    int s, d;
    if (g_is64) {
        const long long* p = (const long long*)edges;
        s = (int)p[e];
        d = (int)p[(size_t)E + e];
    } else {
        const int* p = (const int*)edges;
        s = p[e];
        d = p[E + e];
    }
    int pos = g_rowptr[d] + atomicAdd(&g_cursor[d], 1);
    g_csr[pos] = s;
}

// ---------------- GEMM: Y[N, DOUT](fp16) = X[N,128](fp32) @ W[128, DOUT] ----
// W fully staged in SMEM; 32 rows/block, 8 warps, 4 rows/warp, DOUT/32 cols/lane.
template <int DOUT>
__global__ void gemm_kernel(const float* __restrict__ X, const float* __restrict__ W,
                            __half* __restrict__ Y) {
    extern __shared__ float smem[];
    float* sW = smem;                // 128 * DOUT
    float* sX = smem + 128 * DOUT;   // 32 * 128
    int tid = threadIdx.x, wid = tid >> 5, lane = tid & 31;

    for (int i = tid * 4; i < 128 * DOUT; i += 1024)
        *(float4*)&sW[i] = *(const float4*)&W[i];
    int row0 = blockIdx.x * 32;
    for (int i = tid * 4; i < 32 * 128; i += 1024)
        *(float4*)&sX[i] = *(const float4*)&X[(size_t)row0 * 128 + i];
    __syncthreads();

    constexpr int V = DOUT / 32;     // 4 (DOUT=128) or 2 (DOUT=64)
    float acc[4][V];
#pragma unroll
    for (int r = 0; r < 4; r++)
#pragma unroll
        for (int c = 0; c < V; c++) acc[r][c] = 0.0f;

    int r0 = wid * 4;
#pragma unroll 4
    for (int k = 0; k < 128; k++) {
        float wv[V];
        if constexpr (V == 4) {
            float4 t = *(float4*)&sW[k * DOUT + lane * 4];
            wv[0] = t.x; wv[1] = t.y; wv[2] = t.z; wv[3] = t.w;
        } else {
            float2 t = *(float2*)&sW[k * DOUT + lane * 2];
            wv[0] = t.x; wv[1] = t.y;
        }
        float xv[4];
#pragma unroll
        for (int r = 0; r < 4; r++) xv[r] = sX[(r0 + r) * 128 + k];
#pragma unroll
        for (int r = 0; r < 4; r++)
#pragma unroll
            for (int c = 0; c < V; c++) acc[r][c] += xv[r] * wv[c];
    }

#pragma unroll
    for (int r = 0; r < 4; r++) {
        __half* yp = &Y[(size_t)(row0 + r0 + r) * DOUT + lane * V];
        if constexpr (V == 4) {
            __half2 p0 = __floats2half2_rn(acc[r][0], acc[r][1]);
            __half2 p1 = __floats2half2_rn(acc[r][2], acc[r][3]);
            uint2 pk; pk.x = *(unsigned*)&p0; pk.y = *(unsigned*)&p1;
            *(uint2*)yp = pk;
        } else {
            __half2 p0 = __floats2half2_rn(acc[r][0], acc[r][1]);
            *(unsigned*)yp = *(unsigned*)&p0;
        }
    }
}

// ---------------- aggregation: one warp per destination node ----------------
// out[n] = dinv[n]*sum_{s in N(n)} dinv[s]*H[s] + dinv[n]^2*H[n] + bias
// H is fp16 (half gather bytes); accumulation in fp32. 2-edge unroll for MLP.
template <int D, bool RELU>
__global__ void agg_kernel(const __half* __restrict__ H, const float* __restrict__ bias,
                           float* __restrict__ OUT) {
    int gw = (blockIdx.x * blockDim.x + threadIdx.x) >> 5;
    if (gw >= N_NODES) return;
    int lane = threadIdx.x & 31;
    constexpr int V = D / 32;        // halves per lane: 4 (D=128) or 2 (D=64)

    float acc[V];
#pragma unroll
    for (int c = 0; c < V; c++) acc[c] = 0.0f;

    int e = g_rowptr[gw];
    const int e1 = g_rowptr[gw + 1];

    for (; e + 1 < e1; e += 2) {
        int s0 = __ldg(&g_csr[e]);
        int s1 = __ldg(&g_csr[e + 1]);
        float w0 = __ldg(&g_dinv[s0]);
        float w1 = __ldg(&g_dinv[s1]);
        if constexpr (V == 4) {
            uint2 a = *(const uint2*)&H[(size_t)s0 * D + lane * 4];
            uint2 b = *(const uint2*)&H[(size_t)s1 * D + lane * 4];
            float2 a0 = __half22float2(*(__half2*)&a.x);
            float2 a1v = __half22float2(*(__half2*)&a.y);
            float2 b0 = __half22float2(*(__half2*)&b.x);
            float2 b1v = __half22float2(*(__half2*)&b.y);
            acc[0] += w0 * a0.x + w1 * b0.x;
            acc[1] += w0 * a0.y + w1 * b0.y;
            acc[2] += w0 * a1v.x + w1 * b1v.x;
            acc[3] += w0 * a1v.y + w1 * b1v.y;
        } else {
            unsigned a = *(const unsigned*)&H[(size_t)s0 * D + lane * 2];
            unsigned b = *(const unsigned*)&H[(size_t)s1 * D + lane * 2];
            float2 a0 = __half22float2(*(__half2*)&a);
            float2 b0 = __half22float2(*(__half2*)&b);
            acc[0] += w0 * a0.x + w1 * b0.x;
            acc[1] += w0 * a0.y + w1 * b0.y;
        }
    }
    if (e < e1) {
        int s = __ldg(&g_csr[e]);
        float w = __ldg(&g_dinv[s]);
        if constexpr (V == 4) {
            uint2 a = *(const uint2*)&H[(size_t)s * D + lane * 4];
            float2 a0 = __half22float2(*(__half2*)&a.x);
            float2 a1v = __half22float2(*(__half2*)&a.y);
            acc[0] += w * a0.x; acc[1] += w * a0.y;
            acc[2] += w * a1v.x; acc[3] += w * a1v.y;
        } else {
            unsigned a = *(const unsigned*)&H[(size_t)s * D + lane * 2];
            float2 a0 = __half22float2(*(__half2*)&a);
            acc[0] += w * a0.x; acc[1] += w * a0.y;
        }
    }

    float dd = g_dinv[gw];
    float dd2 = dd * dd;
    if constexpr (V == 4) {
        uint2 hsr = *(const uint2*)&H[(size_t)gw * D + lane * 4];
        float2 h0 = __half22float2(*(__half2*)&hsr.x);
        float2 h1v = __half22float2(*(__half2*)&hsr.y);
        float4 bv = *(const float4*)&bias[lane * 4];
        float o0 = dd * acc[0] + dd2 * h0.x + bv.x;
        float o1 = dd * acc[1] + dd2 * h0.y + bv.y;
        float o2 = dd * acc[2] + dd2 * h1v.x + bv.z;
        float o3 = dd * acc[3] + dd2 * h1v.y + bv.w;
        if constexpr (RELU) {
            o0 = fmaxf(o0, 0.0f); o1 = fmaxf(o1, 0.0f);
            o2 = fmaxf(o2, 0.0f); o3 = fmaxf(o3, 0.0f);
        }
        *(float4*)&OUT[(size_t)gw * D + lane * 4] = make_float4(o0, o1, o2, o3);
    } else {
        unsigned hsr = *(const unsigned*)&H[(size_t)gw * D + lane * 2];
        float2 h0 = __half22float2(*(__half2*)&hsr);
        float2 bv = *(const float2*)&bias[lane * 2];
        float o0 = dd * acc[0] + dd2 * h0.x + bv.x;
        float o1 = dd * acc[1] + dd2 * h0.y + bv.y;
        if constexpr (RELU) { o0 = fmaxf(o0, 0.0f); o1 = fmaxf(o1, 0.0f); }
        *(float2*)&OUT[(size_t)gw * D + lane * 2] = make_float2(o0, o1);
    }
}

// ---------------- launch -----------------------------------------------------
extern "C" void kernel_launch(void* const* d_in, const int* in_sizes, int n_in,
                              void* d_out, int out_size) {
    const float* x  = (const float*)d_in[0];
    const void*  ei = d_in[1];
    const float* W1 = (const float*)d_in[2];
    const float* b1 = (const float*)d_in[3];
    const float* W2 = (const float*)d_in[4];
    const float* b2 = (const float*)d_in[5];
    float* out = (float*)d_out;
    int E = in_sizes[1] / 2;

    const int SMEM1 = (128 * 128 + 32 * 128) * 4;   // 80 KB
    const int SMEM2 = (128 * 64 + 32 * 128) * 4;    // 48 KB
    cudaFuncSetAttribute(gemm_kernel<128>, cudaFuncAttributeMaxDynamicSharedMemorySize, SMEM1);
    cudaFuncSetAttribute(gemm_kernel<64>,  cudaFuncAttributeMaxDynamicSharedMemorySize, SMEM2);

    __half *h1, *h2;
    float *a1;
    cudaGetSymbolAddress((void**)&h1, g_h1);
    cudaGetSymbolAddress((void**)&a1, g_a1);
    cudaGetSymbolAddress((void**)&h2, g_h2);

    const int TB = 256;
    int gE = (E + TB - 1) / TB;
    int gN = (N_NODES + TB - 1) / TB;

    // Serial single-stream schedule: overlapping bandwidth-heavy phases
    // thrashes L2 on this chip (measured +268us in R2). Keep phases ordered.
    prep_init_kernel<<<gN, TB>>>((const long long*)ei);
    count_kernel<<<gE, TB>>>(ei, E);
    dinv_kernel<<<gN, TB>>>();
    scan_kernel<<<1, 1024>>>();
    fill_kernel<<<gE, TB>>>(ei, E);

    gemm_kernel<128><<<N_NODES / 32, 256, SMEM1>>>(x, W1, h1);
    agg_kernel<128, true><<<(N_NODES + 7) / 8, 256>>>(h1, b1, a1);
    gemm_kernel<64><<<N_NODES / 32, 256, SMEM2>>>(a1, W2, h2);
    agg_kernel<64, false><<<(N_NODES + 7) / 8, 256>>>(h2, b2, out);
}

// round 7
// speedup vs baseline: 1.9651x; 1.2439x over previous
#include <cuda_runtime.h>
#include <cuda_fp16.h>

#define N_NODES 100000
#define E_MAX   3400000

// ---------------- scratch (device globals; no allocation allowed) ------------
__device__ int   g_cnt[N_NODES];
__device__ int   g_cursor[N_NODES];
__device__ int   g_start[N_NODES];   // CSR segment start (order-free assignment)
__device__ float g_dinv[N_NODES];
__device__ int   g_total;
__device__ int   g_csr[E_MAX];       // src indices grouped by dst
__device__ __align__(16) __half g_h1[(size_t)N_NODES * 128];  // fp16 features for gather
__device__ __align__(16) float  g_a1[(size_t)N_NODES * 128];  // fp32 layer-1 output
__device__ __align__(16) __half g_h2[(size_t)N_NODES * 64];
__device__ int   g_is64;

// ---------------- init + edge dtype detection --------------------------------
__global__ void prep_init_kernel(const long long* __restrict__ edges) {
    int i = blockIdx.x * blockDim.x + threadIdx.x;
    if (i < N_NODES) { g_cnt[i] = 0; g_cursor[i] = 0; }
    if (i == 0) g_total = 0;
    if (blockIdx.x == 0) {
        __shared__ int bad;
        if (threadIdx.x == 0) bad = 0;
        __syncthreads();
        for (int k = threadIdx.x; k < 1024; k += blockDim.x) {
            long long v = edges[k];
            if (v < 0 || v >= N_NODES) bad = 1;   // benign race: all writers store 1
        }
        __syncthreads();
        if (threadIdx.x == 0) g_is64 = bad ? 0 : 1;
    }
}

__global__ void count_kernel(const void* __restrict__ edges, int E) {
    int e = blockIdx.x * blockDim.x + threadIdx.x;
    if (e >= E) return;
    int d;
    if (g_is64) d = (int)((const long long*)edges)[(size_t)E + e];
    else        d = ((const int*)edges)[E + e];
    atomicAdd(&g_cnt[d], 1);
}

// Per-block exclusive scan of degrees; one global atomic per block hands each
// node a disjoint CSR segment (segments need not be in node order). Also
// computes dinv. Replaces the 102us single-block global scan.
__global__ void offset_kernel() {
    int i = blockIdx.x * blockDim.x + threadIdx.x;
    int c = (i < N_NODES) ? g_cnt[i] : 0;
    int lane = threadIdx.x & 31, wid = threadIdx.x >> 5;

    // inclusive warp scan
    int v = c;
#pragma unroll
    for (int o = 1; o < 32; o <<= 1) {
        int t = __shfl_up_sync(0xFFFFFFFFu, v, o);
        if (lane >= o) v += t;
    }

    __shared__ int wsum[8], wbase[8];
    __shared__ int blockbase;
    if (lane == 31) wsum[wid] = v;
    __syncthreads();
    if (threadIdx.x == 0) {
        int run = 0;
#pragma unroll
        for (int w = 0; w < 8; w++) { wbase[w] = run; run += wsum[w]; }
        blockbase = atomicAdd(&g_total, run);
    }
    __syncthreads();

    if (i < N_NODES) {
        g_start[i] = blockbase + wbase[wid] + (v - c);  // exclusive prefix
        g_dinv[i]  = rsqrtf((float)(c + 1));            // +1 = self loop
    }
}

__global__ void fill_kernel(const void* __restrict__ edges, int E) {
    int e = blockIdx.x * blockDim.x + threadIdx.x;
    if (e >= E) return;
    int s, d;
    if (g_is64) {
        const long long* p = (const long long*)edges;
        s = (int)p[e];
        d = (int)p[(size_t)E + e];
    } else {
        const int* p = (const int*)edges;
        s = p[e];
        d = p[E + e];
    }
    int pos = g_start[d] + atomicAdd(&g_cursor[d], 1);
    g_csr[pos] = s;
}

// ---------------- GEMM: Y[N, DOUT](fp16) = X[N,128](fp32) @ W[128, DOUT] ----
template <int DOUT>
__global__ void gemm_kernel(const float* __restrict__ X, const float* __restrict__ W,
                            __half* __restrict__ Y) {
    extern __shared__ float smem[];
    float* sW = smem;                // 128 * DOUT
    float* sX = smem + 128 * DOUT;   // 32 * 128
    int tid = threadIdx.x, wid = tid >> 5, lane = tid & 31;

    for (int i = tid * 4; i < 128 * DOUT; i += 1024)
        *(float4*)&sW[i] = *(const float4*)&W[i];
    int row0 = blockIdx.x * 32;
    for (int i = tid * 4; i < 32 * 128; i += 1024)
        *(float4*)&sX[i] = *(const float4*)&X[(size_t)row0 * 128 + i];
    __syncthreads();

    constexpr int V = DOUT / 32;     // 4 (DOUT=128) or 2 (DOUT=64)
    float acc[4][V];
#pragma unroll
    for (int r = 0; r < 4; r++)
#pragma unroll
        for (int c = 0; c < V; c++) acc[r][c] = 0.0f;

    int r0 = wid * 4;
#pragma unroll 4
    for (int k = 0; k < 128; k++) {
        float wv[V];
        if constexpr (V == 4) {
            float4 t = *(float4*)&sW[k * DOUT + lane * 4];
            wv[0] = t.x; wv[1] = t.y; wv[2] = t.z; wv[3] = t.w;
        } else {
            float2 t = *(float2*)&sW[k * DOUT + lane * 2];
            wv[0] = t.x; wv[1] = t.y;
        }
        float xv[4];
#pragma unroll
        for (int r = 0; r < 4; r++) xv[r] = sX[(r0 + r) * 128 + k];
#pragma unroll
        for (int r = 0; r < 4; r++)
#pragma unroll
            for (int c = 0; c < V; c++) acc[r][c] += xv[r] * wv[c];
    }

#pragma unroll
    for (int r = 0; r < 4; r++) {
        __half* yp = &Y[(size_t)(row0 + r0 + r) * DOUT + lane * V];
        if constexpr (V == 4) {
            __half2 p0 = __floats2half2_rn(acc[r][0], acc[r][1]);
            __half2 p1 = __floats2half2_rn(acc[r][2], acc[r][3]);
            uint2 pk; pk.x = *(unsigned*)&p0; pk.y = *(unsigned*)&p1;
            *(uint2*)yp = pk;
        } else {
            __half2 p0 = __floats2half2_rn(acc[r][0], acc[r][1]);
            *(unsigned*)yp = *(unsigned*)&p0;
        }
    }
}

// ---------------- aggregation: one warp per destination node ----------------
// out[n] = dinv[n]*sum_{s in N(n)} dinv[s]*H[s] + dinv[n]^2*H[n] + bias
// H fp16, fp32 accumulation. 4-edge unroll: all gathers issued before FMAs.
template <int D, bool RELU>
__global__ void agg_kernel(const __half* __restrict__ H, const float* __restrict__ bias,
                           float* __restrict__ OUT) {
    int gw = (blockIdx.x * blockDim.x + threadIdx.x) >> 5;
    if (gw >= N_NODES) return;
    int lane = threadIdx.x & 31;
    constexpr int V = D / 32;        // halves per lane: 4 (D=128) or 2 (D=64)

    float acc[V];
#pragma unroll
    for (int c = 0; c < V; c++) acc[c] = 0.0f;

    int e = g_start[gw];
    const int e1 = e + g_cnt[gw];

    for (; e + 3 < e1; e += 4) {
        int s0 = __ldg(&g_csr[e]);
        int s1 = __ldg(&g_csr[e + 1]);
        int s2 = __ldg(&g_csr[e + 2]);
        int s3 = __ldg(&g_csr[e + 3]);
        float w0 = __ldg(&g_dinv[s0]);
        float w1 = __ldg(&g_dinv[s1]);
        float w2 = __ldg(&g_dinv[s2]);
        float w3 = __ldg(&g_dinv[s3]);
        if constexpr (V == 4) {
            uint2 a = *(const uint2*)&H[(size_t)s0 * D + lane * 4];
            uint2 b = *(const uint2*)&H[(size_t)s1 * D + lane * 4];
            uint2 c = *(const uint2*)&H[(size_t)s2 * D + lane * 4];
            uint2 d = *(const uint2*)&H[(size_t)s3 * D + lane * 4];
            float2 a0 = __half22float2(*(__half2*)&a.x), a1v = __half22float2(*(__half2*)&a.y);
            float2 b0 = __half22float2(*(__half2*)&b.x), b1v = __half22float2(*(__half2*)&b.y);
            float2 c0 = __half22float2(*(__half2*)&c.x), c1v = __half22float2(*(__half2*)&c.y);
            float2 d0 = __half22float2(*(__half2*)&d.x), d1v = __half22float2(*(__half2*)&d.y);
            acc[0] += w0 * a0.x + w1 * b0.x + w2 * c0.x + w3 * d0.x;
            acc[1] += w0 * a0.y + w1 * b0.y + w2 * c0.y + w3 * d0.y;
            acc[2] += w0 * a1v.x + w1 * b1v.x + w2 * c1v.x + w3 * d1v.x;
            acc[3] += w0 * a1v.y + w1 * b1v.y + w2 * c1v.y + w3 * d1v.y;
        } else {
            unsigned a = *(const unsigned*)&H[(size_t)s0 * D + lane * 2];
            unsigned b = *(const unsigned*)&H[(size_t)s1 * D + lane * 2];
            unsigned c = *(const unsigned*)&H[(size_t)s2 * D + lane * 2];
            unsigned d = *(const unsigned*)&H[(size_t)s3 * D + lane * 2];
            float2 a0 = __half22float2(*(__half2*)&a);
            float2 b0 = __half22float2(*(__half2*)&b);
            float2 c0 = __half22float2(*(__half2*)&c);
            float2 d0 = __half22float2(*(__half2*)&d);
            acc[0] += w0 * a0.x + w1 * b0.x + w2 * c0.x + w3 * d0.x;
            acc[1] += w0 * a0.y + w1 * b0.y + w2 * c0.y + w3 * d0.y;
        }
    }
    for (; e < e1; e++) {
        int s = __ldg(&g_csr[e]);
        float w = __ldg(&g_dinv[s]);
        if constexpr (V == 4) {
            uint2 a = *(const uint2*)&H[(size_t)s * D + lane * 4];
            float2 a0 = __half22float2(*(__half2*)&a.x), a1v = __half22float2(*(__half2*)&a.y);
            acc[0] += w * a0.x; acc[1] += w * a0.y;
            acc[2] += w * a1v.x; acc[3] += w * a1v.y;
        } else {
            unsigned a = *(const unsigned*)&H[(size_t)s * D + lane * 2];
            float2 a0 = __half22float2(*(__half2*)&a);
            acc[0] += w * a0.x; acc[1] += w * a0.y;
        }
    }

    float dd = g_dinv[gw];
    float dd2 = dd * dd;
    if constexpr (V == 4) {
        uint2 hsr = *(const uint2*)&H[(size_t)gw * D + lane * 4];
        float2 h0 = __half22float2(*(__half2*)&hsr.x);
        float2 h1v = __half22float2(*(__half2*)&hsr.y);
        float4 bv = *(const float4*)&bias[lane * 4];
        float o0 = dd * acc[0] + dd2 * h0.x + bv.x;
        float o1 = dd * acc[1] + dd2 * h0.y + bv.y;
        float o2 = dd * acc[2] + dd2 * h1v.x + bv.z;
        float o3 = dd * acc[3] + dd2 * h1v.y + bv.w;
        if constexpr (RELU) {
            o0 = fmaxf(o0, 0.0f); o1 = fmaxf(o1, 0.0f);
            o2 = fmaxf(o2, 0.0f); o3 = fmaxf(o3, 0.0f);
        }
        *(float4*)&OUT[(size_t)gw * D + lane * 4] = make_float4(o0, o1, o2, o3);
    } else {
        unsigned hsr = *(const unsigned*)&H[(size_t)gw * D + lane * 2];
        float2 h0 = __half22float2(*(__half2*)&hsr);
        float2 bv = *(const float2*)&bias[lane * 2];
        float o0 = dd * acc[0] + dd2 * h0.x + bv.x;
        float o1 = dd * acc[1] + dd2 * h0.y + bv.y;
        if constexpr (RELU) { o0 = fmaxf(o0, 0.0f); o1 = fmaxf(o1, 0.0f); }
        *(float2*)&OUT[(size_t)gw * D + lane * 2] = make_float2(o0, o1);
    }
}

// ---------------- launch -----------------------------------------------------
extern "C" void kernel_launch(void* const* d_in, const int* in_sizes, int n_in,
                              void* d_out, int out_size) {
    const float* x  = (const float*)d_in[0];
    const void*  ei = d_in[1];
    const float* W1 = (const float*)d_in[2];
    const float* b1 = (const float*)d_in[3];
    const float* W2 = (const float*)d_in[4];
    const float* b2 = (const float*)d_in[5];
    float* out = (float*)d_out;
    int E = in_sizes[1] / 2;

    const int SMEM1 = (128 * 128 + 32 * 128) * 4;   // 80 KB
    const int SMEM2 = (128 * 64 + 32 * 128) * 4;    // 48 KB
    cudaFuncSetAttribute(gemm_kernel<128>, cudaFuncAttributeMaxDynamicSharedMemorySize, SMEM1);
    cudaFuncSetAttribute(gemm_kernel<64>,  cudaFuncAttributeMaxDynamicSharedMemorySize, SMEM2);

    __half *h1, *h2;
    float *a1;
    cudaGetSymbolAddress((void**)&h1, g_h1);
    cudaGetSymbolAddress((void**)&a1, g_a1);
    cudaGetSymbolAddress((void**)&h2, g_h2);

    const int TB = 256;
    int gE = (E + TB - 1) / TB;
    int gN = (N_NODES + TB - 1) / TB;

    // Serial single-stream schedule: overlapping bandwidth-heavy phases
    // thrashes L2 on this chip (measured +268us in R2). Keep phases ordered.
    prep_init_kernel<<<gN, TB>>>((const long long*)ei);
    count_kernel<<<gE, TB>>>(ei, E);
    offset_kernel<<<gN, TB>>>();     // block-scan + 391 atomics; also computes dinv
    fill_kernel<<<gE, TB>>>(ei, E);

    gemm_kernel<128><<<N_NODES / 32, 256, SMEM1>>>(x, W1, h1);
    agg_kernel<128, true><<<(N_NODES + 7) / 8, 256>>>(h1, b1, a1);
    gemm_kernel<64><<<N_NODES / 32, 256, SMEM2>>>(a1, W2, h2);
    agg_kernel<64, false><<<(N_NODES + 7) / 8, 256>>>(h2, b2, out);
}

// round 8
// speedup vs baseline: 2.0441x; 1.0402x over previous
#include <cuda_runtime.h>
#include <cuda_fp16.h>

#define N_NODES 100000
#define E_MAX   3400000

// Packed dual fp32 FMA (sm_103a): d = a*b + c on two fp32 lanes per instr.
// ptxas never auto-generates this; PTX-only. Full IEEE fp32 rounding per lane.
#define FMA_F32X2(d, a, b, c) \
    asm("fma.rn.f32x2 %0, %1, %2, %3;" : "=l"(d) : "l"(a), "l"(b), "l"(c))
#define PACK_F32X2(out, lo, hi) \
    asm("mov.b64 %0, {%1, %2};" : "=l"(out) : "f"(lo), "f"(hi))
#define UNPACK_F32X2(lo, hi, in) \
    asm("mov.b64 {%0, %1}, %2;" : "=f"(lo), "=f"(hi) : "l"(in))

// ---------------- scratch (device globals; no allocation allowed) ------------
__device__ int   g_cnt[N_NODES];
__device__ int   g_cursor[N_NODES];
__device__ int   g_start[N_NODES];   // CSR segment start (order-free assignment)
__device__ float g_dinv[N_NODES];
__device__ int   g_total;
__device__ int   g_csr[E_MAX];       // src indices grouped by dst
__device__ __align__(16) __half g_h1[(size_t)N_NODES * 128];  // fp16 features for gather
__device__ __align__(16) float  g_a1[(size_t)N_NODES * 128];  // fp32 layer-1 output
__device__ __align__(16) __half g_h2[(size_t)N_NODES * 64];
__device__ int   g_is64;

// ---------------- init + edge dtype detection --------------------------------
__global__ void prep_init_kernel(const long long* __restrict__ edges) {
    int i = blockIdx.x * blockDim.x + threadIdx.x;
    if (i < N_NODES) { g_cnt[i] = 0; g_cursor[i] = 0; }
    if (i == 0) g_total = 0;
    if (blockIdx.x == 0) {
        __shared__ int bad;
        if (threadIdx.x == 0) bad = 0;
        __syncthreads();
        for (int k = threadIdx.x; k < 1024; k += blockDim.x) {
            long long v = edges[k];
            if (v < 0 || v >= N_NODES) bad = 1;   // benign race: all writers store 1
        }
        __syncthreads();
        if (threadIdx.x == 0) g_is64 = bad ? 0 : 1;
    }
}

__global__ void count_kernel(const void* __restrict__ edges, int E) {
    int e = blockIdx.x * blockDim.x + threadIdx.x;
    if (e >= E) return;
    int d;
    if (g_is64) d = (int)((const long long*)edges)[(size_t)E + e];
    else        d = ((const int*)edges)[E + e];
    atomicAdd(&g_cnt[d], 1);
}

// Per-block exclusive scan of degrees; one global atomic per block hands each
// node a disjoint CSR segment (segments need not be in node order). Also
// computes dinv.
__global__ void offset_kernel() {
    int i = blockIdx.x * blockDim.x + threadIdx.x;
    int c = (i < N_NODES) ? g_cnt[i] : 0;
    int lane = threadIdx.x & 31, wid = threadIdx.x >> 5;

    int v = c;
#pragma unroll
    for (int o = 1; o < 32; o <<= 1) {
        int t = __shfl_up_sync(0xFFFFFFFFu, v, o);
        if (lane >= o) v += t;
    }

    __shared__ int wsum[8], wbase[8];
    __shared__ int blockbase;
    if (lane == 31) wsum[wid] = v;
    __syncthreads();
    if (threadIdx.x == 0) {
        int run = 0;
#pragma unroll
        for (int w = 0; w < 8; w++) { wbase[w] = run; run += wsum[w]; }
        blockbase = atomicAdd(&g_total, run);
    }
    __syncthreads();

    if (i < N_NODES) {
        g_start[i] = blockbase + wbase[wid] + (v - c);
        g_dinv[i]  = rsqrtf((float)(c + 1));            // +1 = self loop
    }
}

__global__ void fill_kernel(const void* __restrict__ edges, int E) {
    int e = blockIdx.x * blockDim.x + threadIdx.x;
    if (e >= E) return;
    int s, d;
    if (g_is64) {
        const long long* p = (const long long*)edges;
        s = (int)p[e];
        d = (int)p[(size_t)E + e];
    } else {
        const int* p = (const int*)edges;
        s = p[e];
        d = p[E + e];
    }
    int pos = g_start[d] + atomicAdd(&g_cursor[d], 1);
    g_csr[pos] = s;
}

// ---------------- GEMM: Y[N, DOUT](fp16) = X[N,128](fp32) @ W[128, DOUT] ----
// fma.rn.f32x2 inner loop (2 fp32 FMA/issue). x loaded as float4 over k to keep
// the kernel FMA-issue-bound rather than LDS-bound.
template <int DOUT>
__global__ void gemm_kernel(const float* __restrict__ X, const float* __restrict__ W,
                            __half* __restrict__ Y) {
    extern __shared__ float smem[];
    float* sW = smem;                // 128 * DOUT
    float* sX = smem + 128 * DOUT;   // 32 * 128
    int tid = threadIdx.x, wid = tid >> 5, lane = tid & 31;

    for (int i = tid * 4; i < 128 * DOUT; i += 1024)
        *(float4*)&sW[i] = *(const float4*)&W[i];
    int row0 = blockIdx.x * 32;
    for (int i = tid * 4; i < 32 * 128; i += 1024)
        *(float4*)&sX[i] = *(const float4*)&X[(size_t)row0 * 128 + i];
    __syncthreads();

    constexpr int P = DOUT / 64;     // packed-pair accumulators per row: 2 or 1
    unsigned long long acc[4][P];
#pragma unroll
    for (int r = 0; r < 4; r++)
#pragma unroll
        for (int c = 0; c < P; c++) PACK_F32X2(acc[r][c], 0.0f, 0.0f);

    int r0 = wid * 4;
    const int wcol = (P == 2) ? lane * 4 : lane * 2;

#pragma unroll 2
    for (int k4 = 0; k4 < 128; k4 += 4) {
        float4 xr[4];
#pragma unroll
        for (int r = 0; r < 4; r++) xr[r] = *(float4*)&sX[(r0 + r) * 128 + k4];
#pragma unroll
        for (int kk = 0; kk < 4; kk++) {
            int k = k4 + kk;
            unsigned long long w01, w23;
            if constexpr (P == 2) {
                ulonglong2 wt = *(ulonglong2*)&sW[k * DOUT + wcol];
                w01 = wt.x; w23 = wt.y;
            } else {
                w01 = *(unsigned long long*)&sW[k * DOUT + wcol];
            }
#pragma unroll
            for (int r = 0; r < 4; r++) {
                float xs = (kk == 0) ? xr[r].x : (kk == 1) ? xr[r].y
                         : (kk == 2) ? xr[r].z : xr[r].w;
                unsigned long long xx;
                PACK_F32X2(xx, xs, xs);
                FMA_F32X2(acc[r][0], xx, w01, acc[r][0]);
                if constexpr (P == 2) FMA_F32X2(acc[r][1], xx, w23, acc[r][1]);
            }
        }
    }

#pragma unroll
    for (int r = 0; r < 4; r++) {
        __half* yp = &Y[(size_t)(row0 + r0 + r) * DOUT + wcol];
        float f0, f1;
        UNPACK_F32X2(f0, f1, acc[r][0]);
        __half2 p0 = __floats2half2_rn(f0, f1);
        if constexpr (P == 2) {
            float f2, f3;
            UNPACK_F32X2(f2, f3, acc[r][1]);
            __half2 p1 = __floats2half2_rn(f2, f3);
            uint2 pk; pk.x = *(unsigned*)&p0; pk.y = *(unsigned*)&p1;
            *(uint2*)yp = pk;
        } else {
            *(unsigned*)yp = *(unsigned*)&p0;
        }
    }
}

// ---------------- aggregation: one warp per destination node ----------------
// out[n] = dinv[n]*sum_{s in N(n)} dinv[s]*H[s] + dinv[n]^2*H[n] + bias
// H fp16, fp32 accumulation. 4-edge unroll: all gathers issued before FMAs.
template <int D, bool RELU>
__global__ void agg_kernel(const __half* __restrict__ H, const float* __restrict__ bias,
                           float* __restrict__ OUT) {
    int gw = (blockIdx.x * blockDim.x + threadIdx.x) >> 5;
    if (gw >= N_NODES) return;
    int lane = threadIdx.x & 31;
    constexpr int V = D / 32;        // halves per lane: 4 (D=128) or 2 (D=64)

    float acc[V];
#pragma unroll
    for (int c = 0; c < V; c++) acc[c] = 0.0f;

    int e = g_start[gw];
    const int e1 = e + g_cnt[gw];

    for (; e + 3 < e1; e += 4) {
        int s0 = __ldg(&g_csr[e]);
        int s1 = __ldg(&g_csr[e + 1]);
        int s2 = __ldg(&g_csr[e + 2]);
        int s3 = __ldg(&g_csr[e + 3]);
        float w0 = __ldg(&g_dinv[s0]);
        float w1 = __ldg(&g_dinv[s1]);
        float w2 = __ldg(&g_dinv[s2]);
        float w3 = __ldg(&g_dinv[s3]);
        if constexpr (V == 4) {
            uint2 a = *(const uint2*)&H[(size_t)s0 * D + lane * 4];
            uint2 b = *(const uint2*)&H[(size_t)s1 * D + lane * 4];
            uint2 c = *(const uint2*)&H[(size_t)s2 * D + lane * 4];
            uint2 d = *(const uint2*)&H[(size_t)s3 * D + lane * 4];
            float2 a0 = __half22float2(*(__half2*)&a.x), a1v = __half22float2(*(__half2*)&a.y);
            float2 b0 = __half22float2(*(__half2*)&b.x), b1v = __half22float2(*(__half2*)&b.y);
            float2 c0 = __half22float2(*(__half2*)&c.x), c1v = __half22float2(*(__half2*)&c.y);
            float2 d0 = __half22float2(*(__half2*)&d.x), d1v = __half22float2(*(__half2*)&d.y);
            acc[0] += w0 * a0.x + w1 * b0.x + w2 * c0.x + w3 * d0.x;
            acc[1] += w0 * a0.y + w1 * b0.y + w2 * c0.y + w3 * d0.y;
            acc[2] += w0 * a1v.x + w1 * b1v.x + w2 * c1v.x + w3 * d1v.x;
            acc[3] += w0 * a1v.y + w1 * b1v.y + w2 * c1v.y + w3 * d1v.y;
        } else {
            unsigned a = *(const unsigned*)&H[(size_t)s0 * D + lane * 2];
            unsigned b = *(const unsigned*)&H[(size_t)s1 * D + lane * 2];
            unsigned c = *(const unsigned*)&H[(size_t)s2 * D + lane * 2];
            unsigned d = *(const unsigned*)&H[(size_t)s3 * D + lane * 2];
            float2 a0 = __half22float2(*(__half2*)&a);
            float2 b0 = __half22float2(*(__half2*)&b);
            float2 c0 = __half22float2(*(__half2*)&c);
            float2 d0 = __half22float2(*(__half2*)&d);
            acc[0] += w0 * a0.x + w1 * b0.x + w2 * c0.x + w3 * d0.x;
            acc[1] += w0 * a0.y + w1 * b0.y + w2 * c0.y + w3 * d0.y;
        }
    }
    for (; e < e1; e++) {
        int s = __ldg(&g_csr[e]);
        float w = __ldg(&g_dinv[s]);
        if constexpr (V == 4) {
            uint2 a = *(const uint2*)&H[(size_t)s * D + lane * 4];
            float2 a0 = __half22float2(*(__half2*)&a.x), a1v = __half22float2(*(__half2*)&a.y);
            acc[0] += w * a0.x; acc[1] += w * a0.y;
            acc[2] += w * a1v.x; acc[3] += w * a1v.y;
        } else {
            unsigned a = *(const unsigned*)&H[(size_t)s * D + lane * 2];
            float2 a0 = __half22float2(*(__half2*)&a);
            acc[0] += w * a0.x; acc[1] += w * a0.y;
        }
    }

    float dd = g_dinv[gw];
    float dd2 = dd * dd;
    if constexpr (V == 4) {
        uint2 hsr = *(const uint2*)&H[(size_t)gw * D + lane * 4];
        float2 h0 = __half22float2(*(__half2*)&hsr.x);
        float2 h1v = __half22float2(*(__half2*)&hsr.y);
        float4 bv = *(const float4*)&bias[lane * 4];
        float o0 = dd * acc[0] + dd2 * h0.x + bv.x;
        float o1 = dd * acc[1] + dd2 * h0.y + bv.y;
        float o2 = dd * acc[2] + dd2 * h1v.x + bv.z;
        float o3 = dd * acc[3] + dd2 * h1v.y + bv.w;
        if constexpr (RELU) {
            o0 = fmaxf(o0, 0.0f); o1 = fmaxf(o1, 0.0f);
            o2 = fmaxf(o2, 0.0f); o3 = fmaxf(o3, 0.0f);
        }
        *(float4*)&OUT[(size_t)gw * D + lane * 4] = make_float4(o0, o1, o2, o3);
    } else {
        unsigned hsr = *(const unsigned*)&H[(size_t)gw * D + lane * 2];
        float2 h0 = __half22float2(*(__half2*)&hsr);
        float2 bv = *(const float2*)&bias[lane * 2];
        float o0 = dd * acc[0] + dd2 * h0.x + bv.x;
        float o1 = dd * acc[1] + dd2 * h0.y + bv.y;
        if constexpr (RELU) { o0 = fmaxf(o0, 0.0f); o1 = fmaxf(o1, 0.0f); }
        *(float2*)&OUT[(size_t)gw * D + lane * 2] = make_float2(o0, o1);
    }
}

// ---------------- launch -----------------------------------------------------
extern "C" void kernel_launch(void* const* d_in, const int* in_sizes, int n_in,
                              void* d_out, int out_size) {
    const float* x  = (const float*)d_in[0];
    const void*  ei = d_in[1];
    const float* W1 = (const float*)d_in[2];
    const float* b1 = (const float*)d_in[3];
    const float* W2 = (const float*)d_in[4];
    const float* b2 = (const float*)d_in[5];
    float* out = (float*)d_out;
    int E = in_sizes[1] / 2;

    const int SMEM1 = (128 * 128 + 32 * 128) * 4;   // 80 KB
    const int SMEM2 = (128 * 64 + 32 * 128) * 4;    // 48 KB
    cudaFuncSetAttribute(gemm_kernel<128>, cudaFuncAttributeMaxDynamicSharedMemorySize, SMEM1);
    cudaFuncSetAttribute(gemm_kernel<64>,  cudaFuncAttributeMaxDynamicSharedMemorySize, SMEM2);

    __half *h1, *h2;
    float *a1;
    cudaGetSymbolAddress((void**)&h1, g_h1);
    cudaGetSymbolAddress((void**)&a1, g_a1);
    cudaGetSymbolAddress((void**)&h2, g_h2);

    const int TB = 256;
    int gE = (E + TB - 1) / TB;
    int gN = (N_NODES + TB - 1) / TB;

    // Serial single-stream schedule: overlapping bandwidth-heavy phases
    // thrashes L2 on this chip (measured +268us in R2). Keep phases ordered.
    prep_init_kernel<<<gN, TB>>>((const long long*)ei);
    count_kernel<<<gE, TB>>>(ei, E);
    offset_kernel<<<gN, TB>>>();     // block-scan + 391 atomics; also computes dinv
    fill_kernel<<<gE, TB>>>(ei, E);

    gemm_kernel<128><<<N_NODES / 32, 256, SMEM1>>>(x, W1, h1);
    agg_kernel<128, true><<<(N_NODES + 7) / 8, 256>>>(h1, b1, a1);
    gemm_kernel<64><<<N_NODES / 32, 256, SMEM2>>>(a1, W2, h2);
    agg_kernel<64, false><<<(N_NODES + 7) / 8, 256>>>(h2, b2, out);
}

// round 9
// speedup vs baseline: 2.3647x; 1.1569x over previous
#include <cuda_runtime.h>
#include <cuda_fp16.h>

#define N_NODES 100000
#define E_MAX   3400000

// ---------------- scratch (device globals; no allocation allowed) ------------
__device__ int   g_cnt[N_NODES];
__device__ int   g_cursor[N_NODES];
__device__ int   g_start[N_NODES];   // CSR segment start (order-free assignment)
__device__ float g_dinv[N_NODES];
__device__ int   g_total;
__device__ int   g_csr[E_MAX];       // src indices grouped by dst
__device__ __align__(16) __half g_h1[(size_t)N_NODES * 128];  // fp16 features for gather
__device__ __align__(16) float  g_a1[(size_t)N_NODES * 128];  // fp32 layer-1 output
__device__ __align__(16) __half g_h2[(size_t)N_NODES * 64];
__device__ int   g_is64;

__device__ __forceinline__ unsigned to_tf32(float f) {
    unsigned r;
    asm("cvt.rna.tf32.f32 %0, %1;" : "=r"(r) : "f"(f));
    return r;
}

// ---------------- init + edge dtype detection --------------------------------
__global__ void prep_init_kernel(const long long* __restrict__ edges) {
    int i = blockIdx.x * blockDim.x + threadIdx.x;
    if (i < N_NODES) { g_cnt[i] = 0; g_cursor[i] = 0; }
    if (i == 0) g_total = 0;
    if (blockIdx.x == 0) {
        __shared__ int bad;
        if (threadIdx.x == 0) bad = 0;
        __syncthreads();
        for (int k = threadIdx.x; k < 1024; k += blockDim.x) {
            long long v = edges[k];
            if (v < 0 || v >= N_NODES) bad = 1;   // benign race: all writers store 1
        }
        __syncthreads();
        if (threadIdx.x == 0) g_is64 = bad ? 0 : 1;
    }
}

__global__ void count_kernel(const void* __restrict__ edges, int E) {
    int e = blockIdx.x * blockDim.x + threadIdx.x;
    if (e >= E) return;
    int d;
    if (g_is64) d = (int)((const long long*)edges)[(size_t)E + e];
    else        d = ((const int*)edges)[E + e];
    atomicAdd(&g_cnt[d], 1);
}

// Per-block exclusive scan of degrees; one global atomic per block hands each
// node a disjoint CSR segment (segments need not be in node order). Also
// computes dinv.
__global__ void offset_kernel() {
    int i = blockIdx.x * blockDim.x + threadIdx.x;
    int c = (i < N_NODES) ? g_cnt[i] : 0;
    int lane = threadIdx.x & 31, wid = threadIdx.x >> 5;

    int v = c;
#pragma unroll
    for (int o = 1; o < 32; o <<= 1) {
        int t = __shfl_up_sync(0xFFFFFFFFu, v, o);
        if (lane >= o) v += t;
    }

    __shared__ int wsum[8], wbase[8];
    __shared__ int blockbase;
    if (lane == 31) wsum[wid] = v;
    __syncthreads();
    if (threadIdx.x == 0) {
        int run = 0;
#pragma unroll
        for (int w = 0; w < 8; w++) { wbase[w] = run; run += wsum[w]; }
        blockbase = atomicAdd(&g_total, run);
    }
    __syncthreads();

    if (i < N_NODES) {
        g_start[i] = blockbase + wbase[wid] + (v - c);
        g_dinv[i]  = rsqrtf((float)(c + 1));            // +1 = self loop
    }
}

__global__ void fill_kernel(const void* __restrict__ edges, int E) {
    int e = blockIdx.x * blockDim.x + threadIdx.x;
    if (e >= E) return;
    int s, d;
    if (g_is64) {
        const long long* p = (const long long*)edges;
        s = (int)p[e];
        d = (int)p[(size_t)E + e];
    } else {
        const int* p = (const int*)edges;
        s = p[e];
        d = p[E + e];
    }
    int pos = g_start[d] + atomicAdd(&g_cursor[d], 1);
    g_csr[pos] = s;
}

// ---------------- GEMM: Y[N, DOUT](fp16) = X[N,128](fp32) @ W[128, DOUT] ----
// tf32 mma.sync.m16n8k8. 256 threads / 8 warps; 64 rows per block.
// warp (wid&3) -> 16-row strip, (wid>>2) -> DOUT/2 column half.
// SMEM rows padded +4 floats: A-fragment banks = (4*g + tig) -> conflict-free.
template <int DOUT>
__global__ void gemm_mma_kernel(const float* __restrict__ X, const float* __restrict__ W,
                                __half* __restrict__ Y) {
    constexpr int XW = 128 + 4;      // padded X row (floats)
    constexpr int WW = DOUT + 4;     // padded W row
    extern __shared__ float smem[];
    float* sX = smem;                // 64 * XW
    float* sW = smem + 64 * XW;      // 128 * WW

    int tid = threadIdx.x, lane = tid & 31, wid = tid >> 5;
    int row0 = blockIdx.x * 64;

    // stage X (64 x 128) with tf32 rounding
    for (int i = tid; i < 64 * 32; i += 256) {
        int r = i >> 5, c4 = (i & 31) * 4;
        int gr = row0 + r; if (gr >= N_NODES) gr = N_NODES - 1;
        float4 v = *(const float4*)&X[(size_t)gr * 128 + c4];
        float* dst = &sX[r * XW + c4];
        dst[0] = __uint_as_float(to_tf32(v.x));
        dst[1] = __uint_as_float(to_tf32(v.y));
        dst[2] = __uint_as_float(to_tf32(v.z));
        dst[3] = __uint_as_float(to_tf32(v.w));
    }
    // stage W (128 x DOUT) with tf32 rounding
    for (int i = tid; i < 128 * (DOUT / 4); i += 256) {
        int r = i / (DOUT / 4), c4 = (i % (DOUT / 4)) * 4;
        float4 v = *(const float4*)&W[(size_t)r * DOUT + c4];
        float* dst = &sW[r * WW + c4];
        dst[0] = __uint_as_float(to_tf32(v.x));
        dst[1] = __uint_as_float(to_tf32(v.y));
        dst[2] = __uint_as_float(to_tf32(v.z));
        dst[3] = __uint_as_float(to_tf32(v.w));
    }
    __syncthreads();

    constexpr int NT = DOUT / 16;    // m16n8 tiles per warp: 8 (128) or 4 (64)
    int wr = (wid & 3) * 16;         // warp row offset within block
    int wn = (wid >> 2) * (DOUT / 2);// warp col offset
    int g = lane >> 2, tig = lane & 3;

    float c[NT][4];
#pragma unroll
    for (int nt = 0; nt < NT; nt++)
#pragma unroll
        for (int j = 0; j < 4; j++) c[nt][j] = 0.0f;

#pragma unroll
    for (int ks = 0; ks < 16; ks++) {
        int k0 = ks * 8;
        unsigned a0 = __float_as_uint(sX[(wr + g)     * XW + k0 + tig]);
        unsigned a1 = __float_as_uint(sX[(wr + g + 8) * XW + k0 + tig]);
        unsigned a2 = __float_as_uint(sX[(wr + g)     * XW + k0 + tig + 4]);
        unsigned a3 = __float_as_uint(sX[(wr + g + 8) * XW + k0 + tig + 4]);
#pragma unroll
        for (int nt = 0; nt < NT; nt++) {
            unsigned b0 = __float_as_uint(sW[(k0 + tig)     * WW + wn + nt * 8 + g]);
            unsigned b1 = __float_as_uint(sW[(k0 + tig + 4) * WW + wn + nt * 8 + g]);
            asm("mma.sync.aligned.m16n8k8.row.col.f32.tf32.tf32.f32 "
                "{%0,%1,%2,%3}, {%4,%5,%6,%7}, {%8,%9}, {%0,%1,%2,%3};"
                : "+f"(c[nt][0]), "+f"(c[nt][1]), "+f"(c[nt][2]), "+f"(c[nt][3])
                : "r"(a0), "r"(a1), "r"(a2), "r"(a3), "r"(b0), "r"(b1));
        }
    }

    // epilogue: fp16 store. c0/c1 -> row g, cols tig*2, tig*2+1; c2/c3 -> row g+8.
    int r1 = row0 + wr + g;
    int r2 = r1 + 8;
#pragma unroll
    for (int nt = 0; nt < NT; nt++) {
        int col = wn + nt * 8 + tig * 2;
        __half2 p0 = __floats2half2_rn(c[nt][0], c[nt][1]);
        __half2 p1 = __floats2half2_rn(c[nt][2], c[nt][3]);
        if (r1 < N_NODES) *(unsigned*)&Y[(size_t)r1 * DOUT + col] = *(unsigned*)&p0;
        if (r2 < N_NODES) *(unsigned*)&Y[(size_t)r2 * DOUT + col] = *(unsigned*)&p1;
    }
}

// ---------------- aggregation: one warp per destination node ----------------
// out[n] = dinv[n]*sum_{s in N(n)} dinv[s]*H[s] + dinv[n]^2*H[n] + bias
// H fp16, fp32 accumulation. 4-edge unroll: all gathers issued before FMAs.
template <int D, bool RELU>
__global__ void agg_kernel(const __half* __restrict__ H, const float* __restrict__ bias,
                           float* __restrict__ OUT) {
    int gw = (blockIdx.x * blockDim.x + threadIdx.x) >> 5;
    if (gw >= N_NODES) return;
    int lane = threadIdx.x & 31;
    constexpr int V = D / 32;        // halves per lane: 4 (D=128) or 2 (D=64)

    float acc[V];
#pragma unroll
    for (int c = 0; c < V; c++) acc[c] = 0.0f;

    int e = g_start[gw];
    const int e1 = e + g_cnt[gw];

    for (; e + 3 < e1; e += 4) {
        int s0 = __ldg(&g_csr[e]);
        int s1 = __ldg(&g_csr[e + 1]);
        int s2 = __ldg(&g_csr[e + 2]);
        int s3 = __ldg(&g_csr[e + 3]);
        float w0 = __ldg(&g_dinv[s0]);
        float w1 = __ldg(&g_dinv[s1]);
        float w2 = __ldg(&g_dinv[s2]);
        float w3 = __ldg(&g_dinv[s3]);
        if constexpr (V == 4) {
            uint2 a = *(const uint2*)&H[(size_t)s0 * D + lane * 4];
            uint2 b = *(const uint2*)&H[(size_t)s1 * D + lane * 4];
            uint2 c = *(const uint2*)&H[(size_t)s2 * D + lane * 4];
            uint2 d = *(const uint2*)&H[(size_t)s3 * D + lane * 4];
            float2 a0 = __half22float2(*(__half2*)&a.x), a1v = __half22float2(*(__half2*)&a.y);
            float2 b0 = __half22float2(*(__half2*)&b.x), b1v = __half22float2(*(__half2*)&b.y);
            float2 c0 = __half22float2(*(__half2*)&c.x), c1v = __half22float2(*(__half2*)&c.y);
            float2 d0 = __half22float2(*(__half2*)&d.x), d1v = __half22float2(*(__half2*)&d.y);
            acc[0] += w0 * a0.x + w1 * b0.x + w2 * c0.x + w3 * d0.x;
            acc[1] += w0 * a0.y + w1 * b0.y + w2 * c0.y + w3 * d0.y;
            acc[2] += w0 * a1v.x + w1 * b1v.x + w2 * c1v.x + w3 * d1v.x;
            acc[3] += w0 * a1v.y + w1 * b1v.y + w2 * c1v.y + w3 * d1v.y;
        } else {
            unsigned a = *(const unsigned*)&H[(size_t)s0 * D + lane * 2];
            unsigned b = *(const unsigned*)&H[(size_t)s1 * D + lane * 2];
            unsigned c = *(const unsigned*)&H[(size_t)s2 * D + lane * 2];
            unsigned d = *(const unsigned*)&H[(size_t)s3 * D + lane * 2];
            float2 a0 = __half22float2(*(__half2*)&a);
            float2 b0 = __half22float2(*(__half2*)&b);
            float2 c0 = __half22float2(*(__half2*)&c);
            float2 d0 = __half22float2(*(__half2*)&d);
            acc[0] += w0 * a0.x + w1 * b0.x + w2 * c0.x + w3 * d0.x;
            acc[1] += w0 * a0.y + w1 * b0.y + w2 * c0.y + w3 * d0.y;
        }
    }
    for (; e < e1; e++) {
        int s = __ldg(&g_csr[e]);
        float w = __ldg(&g_dinv[s]);
        if constexpr (V == 4) {
            uint2 a = *(const uint2*)&H[(size_t)s * D + lane * 4];
            float2 a0 = __half22float2(*(__half2*)&a.x), a1v = __half22float2(*(__half2*)&a.y);
            acc[0] += w * a0.x; acc[1] += w * a0.y;
            acc[2] += w * a1v.x; acc[3] += w * a1v.y;
        } else {
            unsigned a = *(const unsigned*)&H[(size_t)s * D + lane * 2];
            float2 a0 = __half22float2(*(__half2*)&a);
            acc[0] += w * a0.x; acc[1] += w * a0.y;
        }
    }

    float dd = g_dinv[gw];
    float dd2 = dd * dd;
    if constexpr (V == 4) {
        uint2 hsr = *(const uint2*)&H[(size_t)gw * D + lane * 4];
        float2 h0 = __half22float2(*(__half2*)&hsr.x);
        float2 h1v = __half22float2(*(__half2*)&hsr.y);
        float4 bv = *(const float4*)&bias[lane * 4];
        float o0 = dd * acc[0] + dd2 * h0.x + bv.x;
        float o1 = dd * acc[1] + dd2 * h0.y + bv.y;
        float o2 = dd * acc[2] + dd2 * h1v.x + bv.z;
        float o3 = dd * acc[3] + dd2 * h1v.y + bv.w;
        if constexpr (RELU) {
            o0 = fmaxf(o0, 0.0f); o1 = fmaxf(o1, 0.0f);
            o2 = fmaxf(o2, 0.0f); o3 = fmaxf(o3, 0.0f);
        }
        *(float4*)&OUT[(size_t)gw * D + lane * 4] = make_float4(o0, o1, o2, o3);
    } else {
        unsigned hsr = *(const unsigned*)&H[(size_t)gw * D + lane * 2];
        float2 h0 = __half22float2(*(__half2*)&hsr);
        float2 bv = *(const float2*)&bias[lane * 2];
        float o0 = dd * acc[0] + dd2 * h0.x + bv.x;
        float o1 = dd * acc[1] + dd2 * h0.y + bv.y;
        if constexpr (RELU) { o0 = fmaxf(o0, 0.0f); o1 = fmaxf(o1, 0.0f); }
        *(float2*)&OUT[(size_t)gw * D + lane * 2] = make_float2(o0, o1);
    }
}

// ---------------- launch -----------------------------------------------------
extern "C" void kernel_launch(void* const* d_in, const int* in_sizes, int n_in,
                              void* d_out, int out_size) {
    const float* x  = (const float*)d_in[0];
    const void*  ei = d_in[1];
    const float* W1 = (const float*)d_in[2];
    const float* b1 = (const float*)d_in[3];
    const float* W2 = (const float*)d_in[4];
    const float* b2 = (const float*)d_in[5];
    float* out = (float*)d_out;
    int E = in_sizes[1] / 2;

    const int SMEM1 = (64 * 132 + 128 * 132) * 4;   // ~99 KB
    const int SMEM2 = (64 * 132 + 128 * 68) * 4;    // ~67 KB
    cudaFuncSetAttribute(gemm_mma_kernel<128>, cudaFuncAttributeMaxDynamicSharedMemorySize, SMEM1);
    cudaFuncSetAttribute(gemm_mma_kernel<64>,  cudaFuncAttributeMaxDynamicSharedMemorySize, SMEM2);

    __half *h1, *h2;
    float *a1;
    cudaGetSymbolAddress((void**)&h1, g_h1);
    cudaGetSymbolAddress((void**)&a1, g_a1);
    cudaGetSymbolAddress((void**)&h2, g_h2);

    const int TB = 256;
    int gE = (E + TB - 1) / TB;
    int gN = (N_NODES + TB - 1) / TB;
    int gG = (N_NODES + 63) / 64;

    // Serial single-stream schedule: overlapping bandwidth-heavy phases
    // thrashes L2 on this chip (measured +268us in R2). Keep phases ordered.
    prep_init_kernel<<<gN, TB>>>((const long long*)ei);
    count_kernel<<<gE, TB>>>(ei, E);
    offset_kernel<<<gN, TB>>>();     // block-scan + 391 atomics; also computes dinv
    fill_kernel<<<gE, TB>>>(ei, E);

    gemm_mma_kernel<128><<<gG, 256, SMEM1>>>(x, W1, h1);
    agg_kernel<128, true><<<(N_NODES + 7) / 8, 256>>>(h1, b1, a1);
    gemm_mma_kernel<64><<<gG, 256, SMEM2>>>(a1, W2, h2);
    agg_kernel<64, false><<<(N_NODES + 7) / 8, 256>>>(h2, b2, out);
}